// round 7
// baseline (speedup 1.0000x reference)
#include <cuda_runtime.h>
#include <cuda_bf16.h>
#include <cstdint>

#define BB 32
#define TT 2048
#define VV 128
#define LL 256
#define SS 513            // 2*L+1
#define NTHR 160          // 5 warps; 4 states/thread -> 640 >= 513
#define NWARP 5
#define EDEAD (-(1 << 28))
#define LN2F 0.6931471805599453f

// Scratch: penalty-adjusted softmax probabilities [B][T][V]  (~33.5 MB)
__device__ __align__(16) float g_p[(size_t)BB * TT * VV];
__device__ float g_loss[BB];

__device__ __forceinline__ float penalty_of(int v) {
    if (v == 0 || v == 3) return 1.0f;
    if (v == 11 || v == 15 || v == 19 || v == 25 || v == 31) return 5.0f;
    return 0.0f;
}

// 2^d, exact, flushes to 0 for d < -126. Callers guarantee d <= 127.
__device__ __forceinline__ float p2n(int d) {
    int be = 127 + d;
    be = be < 0 ? 0 : be;
    return __int_as_float((uint32_t)be << 23);
}

// (mo, eo) <- normalize of value (ma*2^ea + mb*2^eb) * q    [2-source state]
__device__ __forceinline__ void upd2(float ma, int ea, float mb, int eb, float q,
                                     float& mo, int& eo) {
    int em = max(ea, eb);
    float a = fmaf(ma, p2n(ea - em), mb * p2n(eb - em)) * q;
    int bits = __float_as_int(a);
    int ad = (bits >> 23) - 127;
    eo = em + ad;
    mo = a * p2n(-ad);          // exact 2^-ad; a==0 stays 0
}

// 3-source state (self, s-1, gated skip s-2)
__device__ __forceinline__ void upd3(float ma, int ea, float mb, int eb,
                                     float mc, int ec, float q,
                                     float& mo, int& eo) {
    int em = max(ea, max(eb, ec));
    float a = fmaf(ma, p2n(ea - em),
              fmaf(mb, p2n(eb - em), mc * p2n(ec - em))) * q;
    int bits = __float_as_int(a);
    int ad = (bits >> 23) - 127;
    eo = em + ad;
    mo = a * p2n(-ad);
}

// ---------------------------------------------------------------------------
// Pass 1: p[b,t,v] = softmax_v(y_pred - penalty)   (linear domain)
// ---------------------------------------------------------------------------
__global__ void prob_kernel(const float* __restrict__ y_pred) {
    int gwarp = (blockIdx.x * blockDim.x + threadIdx.x) >> 5;
    int lane  = threadIdx.x & 31;
    if (gwarp >= BB * TT) return;

    const float4* row = reinterpret_cast<const float4*>(y_pred + (size_t)gwarp * VV);
    float4 x = row[lane];
    int v0 = lane * 4;
    x.x -= penalty_of(v0 + 0);
    x.y -= penalty_of(v0 + 1);
    x.z -= penalty_of(v0 + 2);
    x.w -= penalty_of(v0 + 3);

    float m = fmaxf(fmaxf(x.x, x.y), fmaxf(x.z, x.w));
    #pragma unroll
    for (int o = 16; o > 0; o >>= 1)
        m = fmaxf(m, __shfl_xor_sync(0xffffffffu, m, o));

    float s = __expf(x.x - m) + __expf(x.y - m) + __expf(x.z - m) + __expf(x.w - m);
    #pragma unroll
    for (int o = 16; o > 0; o >>= 1)
        s += __shfl_xor_sync(0xffffffffu, s, o);

    float lse = m + __logf(s);
    float4 out;
    out.x = __expf(x.x - lse);
    out.y = __expf(x.y - lse);
    out.z = __expf(x.z - lse);
    out.w = __expf(x.w - lse);
    reinterpret_cast<float4*>(g_p + (size_t)gwarp * VV)[lane] = out;
}

// ---------------------------------------------------------------------------
// Pass 2: CTC forward, per-state (mantissa, exponent), 4 states per thread.
// Thread i owns states 4i..4i+3. Cross-thread data per step: only state 4i-1
// (shfl within warp, smem halo across warp boundary). One barrier per step.
// ---------------------------------------------------------------------------
__global__ void __launch_bounds__(NTHR, 1) ctc_kernel(const int* __restrict__ y_true) {
    __shared__ float hM[2][NWARP + 1];
    __shared__ int   hE[2][NWARP + 1];
    __shared__ int   sh_lab[LL];
    __shared__ int   sh_len;
    __shared__ float sM[4 * NTHR];
    __shared__ int   sG[4 * NTHR];

    const int b    = blockIdx.x;
    const int tid  = threadIdx.x;
    const int lane = tid & 31;
    const int w    = tid >> 5;

    for (int i = tid; i < LL; i += NTHR) sh_lab[i] = y_true[b * LL + i];
    if (tid == 0) {
        sh_len = 0;
        hM[0][0] = 0.0f;  hM[1][0] = 0.0f;   // state -1: never exists
        hE[0][0] = EDEAD; hE[1][0] = EDEAD;
    }
    __syncthreads();
    for (int i = tid; i < LL; i += NTHR) if (sh_lab[i] != 0) atomicAdd(&sh_len, 1);

    // states s0..s0+3; odd states s0+1 (label ext1), s0+3 (label ext3)
    const int  s0 = 4 * tid;
    const bool r1 = (s0 + 1 < SS);
    const bool r3 = (s0 + 3 < SS);
    int ext1 = 0, ext3 = 0;
    bool skip1 = false, skip3 = false;
    if (r1) ext1 = sh_lab[2 * tid];
    if (r3) ext3 = sh_lab[2 * tid + 1];
    if (r1 && tid > 0) skip1 = (ext1 != 0) && (ext1 != sh_lab[2 * tid - 1]);
    if (r3)            skip3 = (ext3 != 0) && (ext3 != ext1);

    const float* pb = g_p + (size_t)b * TT * VV;

    // ----- t=0 init: only states 0 and 1 live -----
    float m0 = 0.f, m1 = 0.f, m2 = 0.f, m3 = 0.f;
    int   e0 = EDEAD, e1 = EDEAD, e2 = EDEAD, e3 = EDEAD;
    if (tid == 0) {
        float v = pb[0];
        int bits = __float_as_int(v); int e = (bits >> 23) - 127;
        m0 = v * p2n(-e); e0 = e;
        v = pb[ext1];
        bits = __float_as_int(v); e = (bits >> 23) - 127;
        m1 = v * p2n(-e); e1 = e;
    }
    if (lane == 31) {
        hM[0][w + 1] = m3; hE[0][w + 1] = e3;
        hM[1][w + 1] = m3; hE[1][w + 1] = e3;
    }

    // prob queues for t = 1..4 (slot u consumed at t = 4*blk+1+u)
    float qb[4], q1[4], q3[4];
    #pragma unroll
    for (int u = 0; u < 4; ++u) {
        const float* row = pb + (size_t)(1 + u) * VV;
        qb[u] = row[0];
        q1[u] = r1 ? row[ext1] : 0.f;
        q3[u] = r3 ? row[ext3] : 0.f;
    }
    const float* rp = pb + (size_t)5 * VV;   // refill source (row t+4 at t=1)

    __syncthreads();

    for (int blk = 0; blk < 512; ++blk) {
        #pragma unroll
        for (int u = 0; u < 4; ++u) {
            const int t = 4 * blk + 1 + u;
            const int pr = (t - 1) & 1, pw = t & 1;
            if (t < TT) {
                float mLm = __shfl_up_sync(0xffffffffu, m3, 1);
                int   mLe = __shfl_up_sync(0xffffffffu, e3, 1);
                if (lane == 0) { mLm = hM[pr][w]; mLe = hE[pr][w]; }
                const int eSk1 = skip1 ? mLe : EDEAD;
                const int eSk3 = skip3 ? e1  : EDEAD;

                float n0m, n1m, n2m, n3m; int n0e, n1e, n2e, n3e;
                upd2(m0, e0, mLm, mLe, qb[u], n0m, n0e);                 // blank s0
                upd3(m1, e1, m0, e0, mLm, eSk1, q1[u], n1m, n1e);        // label s0+1
                upd2(m2, e2, m1, e1, qb[u], n2m, n2e);                   // blank s0+2
                upd3(m3, e3, m2, e2, m1, eSk3, q3[u], n3m, n3e);         // label s0+3
                m0 = n0m; e0 = n0e; m1 = n1m; e1 = n1e;
                m2 = n2m; e2 = n2e; m3 = n3m; e3 = n3e;
                if (lane == 31) { hM[pw][w + 1] = m3; hE[pw][w + 1] = e3; }
            }
            if (t + 4 < TT) {
                qb[u] = rp[0];
                q1[u] = r1 ? rp[ext1] : 0.f;
                q3[u] = r3 ? rp[ext3] : 0.f;
            }
            rp += VV;
            __syncthreads();
        }
    }

    // ----- readout -----
    sM[s0 + 0] = m0; sM[s0 + 1] = m1; sM[s0 + 2] = m2; sM[s0 + 3] = m3;
    sG[s0 + 0] = e0; sG[s0 + 1] = e1; sG[s0 + 2] = e2; sG[s0 + 3] = e3;
    __syncthreads();
    if (tid == 0) {
        int il = 2 * sh_len, ip = il - 1;    // il in [256, 512]
        float ma = sM[il]; int ga = sG[il];
        float mb = sM[ip]; int gb = sG[ip];
        float la = (ma > 0.f) ? (float)ga + __log2f(ma) : -3.0e8f;
        float lb = (mb > 0.f) ? (float)gb + __log2f(mb) : -3.0e8f;
        float mx = fmaxf(la, lb);
        float ll2 = mx + __log2f(exp2f(la - mx) + exp2f(lb - mx));
        g_loss[b] = -ll2 * LN2F;
    }
}

// ---------------------------------------------------------------------------
// Pass 3: mean over batch + 1e-7
// ---------------------------------------------------------------------------
__global__ void finalize_kernel(float* __restrict__ out) {
    int t = threadIdx.x;
    float v = g_loss[t];
    #pragma unroll
    for (int o = 16; o > 0; o >>= 1)
        v += __shfl_xor_sync(0xffffffffu, v, o);
    if (t == 0) out[0] = v * (1.0f / (float)BB) + 1e-7f;
}

extern "C" void kernel_launch(void* const* d_in, const int* in_sizes, int n_in,
                              void* d_out, int out_size) {
    const float* y_pred = (const float*)d_in[0];
    const int*   y_true = (const int*)d_in[1];
    float*       out    = (float*)d_out;

    prob_kernel<<<(BB * TT) / 8, 256>>>(y_pred);
    ctc_kernel<<<BB, NTHR>>>(y_true);
    finalize_kernel<<<1, 32>>>(out);
}

// round 8
// speedup vs baseline: 1.8638x; 1.8638x over previous
#include <cuda_runtime.h>
#include <cuda_bf16.h>
#include <cstdint>

#define BB 32
#define TT 2048
#define VV 128
#define LL 256
#define SS 513            // 2*L+1
#define NTHR 256          // 8 warps; thread i owns states 2i, 2i+1 (+512 on i=255)
#define NWARP 8
#define EDEAD (-(1 << 28))
#define LN2F 0.6931471805599453f

// Scratch: penalty-adjusted softmax probabilities [B][T][V]  (~33.5 MB)
__device__ __align__(16) float g_p[(size_t)BB * TT * VV];
__device__ float g_loss[BB];

__device__ __forceinline__ float penalty_of(int v) {
    if (v == 0 || v == 3) return 1.0f;
    if (v == 11 || v == 15 || v == 19 || v == 25 || v == 31) return 5.0f;
    return 0.0f;
}

// 2^d, exact; flushes to 0 for d <= -127. Callers guarantee d <= 127.
__device__ __forceinline__ float p2n(int d) {
    int be = 127 + d;
    be = be < 0 ? 0 : be;
    return __int_as_float((uint32_t)be << 23);
}

// ---------------------------------------------------------------------------
// Pass 1: p[b,t,v] = softmax_v(y_pred - penalty)   (linear domain)
// ---------------------------------------------------------------------------
__global__ void prob_kernel(const float* __restrict__ y_pred) {
    int gwarp = (blockIdx.x * blockDim.x + threadIdx.x) >> 5;
    int lane  = threadIdx.x & 31;
    if (gwarp >= BB * TT) return;

    const float4* row = reinterpret_cast<const float4*>(y_pred + (size_t)gwarp * VV);
    float4 x = row[lane];
    int v0 = lane * 4;
    x.x -= penalty_of(v0 + 0);
    x.y -= penalty_of(v0 + 1);
    x.z -= penalty_of(v0 + 2);
    x.w -= penalty_of(v0 + 3);

    float m = fmaxf(fmaxf(x.x, x.y), fmaxf(x.z, x.w));
    #pragma unroll
    for (int o = 16; o > 0; o >>= 1)
        m = fmaxf(m, __shfl_xor_sync(0xffffffffu, m, o));

    float s = __expf(x.x - m) + __expf(x.y - m) + __expf(x.z - m) + __expf(x.w - m);
    #pragma unroll
    for (int o = 16; o > 0; o >>= 1)
        s += __shfl_xor_sync(0xffffffffu, s, o);

    float lse = m + __logf(s);
    float4 out;
    out.x = __expf(x.x - lse);
    out.y = __expf(x.y - lse);
    out.z = __expf(x.z - lse);
    out.w = __expf(x.w - lse);
    reinterpret_cast<float4*>(g_p + (size_t)gwarp * VV)[lane] = out;
}

// ---------------------------------------------------------------------------
// Pass 2: CTC forward. Thread i holds (mE, mO[, mX]) mantissas sharing one
// exponent frame e. Per step: one shfl pair for the neighbor's odd state,
// shared alignment factors, joint renorm. One __syncthreads per step.
// ---------------------------------------------------------------------------
__global__ void __launch_bounds__(NTHR, 1) ctc_kernel(const int* __restrict__ y_true) {
    __shared__ float hM[2][NWARP + 1];
    __shared__ int   hE[2][NWARP + 1];
    __shared__ int   sh_lab[LL];
    __shared__ int   sh_len;
    __shared__ float sM[2 * NTHR + 1];
    __shared__ int   sG[2 * NTHR + 1];

    const int b    = blockIdx.x;
    const int tid  = threadIdx.x;
    const int lane = tid & 31;
    const int w    = tid >> 5;
    const bool last = (tid == NTHR - 1);

    sh_lab[tid] = y_true[b * LL + tid];
    if (tid == 0) {
        sh_len = 0;
        hM[0][0] = 0.0f;  hM[1][0] = 0.0f;    // state -1 (never exists)
        hE[0][0] = EDEAD; hE[1][0] = EDEAD;
    }
    __syncthreads();
    if (sh_lab[tid] != 0) atomicAdd(&sh_len, 1);

    const int ext = sh_lab[tid];               // label of odd state 2*tid+1
    const bool skip = (tid > 0) && (ext != 0) && (ext != sh_lab[tid - 1]);

    const float* pb = g_p + (size_t)b * TT * VV;

    // ----- t=0 init: only states 0, 1 live (thread 0) -----
    float mE = 0.f, mO = 0.f, mX = 0.f;
    int   e  = EDEAD;
    if (tid == 0) {
        float vE = pb[0], vO = pb[ext];
        int eE = (__float_as_int(vE) >> 23) - 127;
        int eO = (__float_as_int(vO) >> 23) - 127;
        e  = max(eE, eO);
        mE = vE * p2n(-e);
        mO = vO * p2n(-e);
    }
    if (lane == 31) {
        hM[0][w + 1] = mO; hE[0][w + 1] = e;
        hM[1][w + 1] = mO; hE[1][w + 1] = e;
    }

    // prob queues for t = 1..4 (slot u consumed at t = 4*blk+1+u)
    float qb[4], q1[4];
    #pragma unroll
    for (int u = 0; u < 4; ++u) {
        const float* row = pb + (size_t)(1 + u) * VV;
        qb[u] = row[0];
        q1[u] = row[ext];
    }
    const float* rp = pb + (size_t)5 * VV;     // refill source (row t+4 at t=1)

    __syncthreads();

    for (int blk = 0; blk < 512; ++blk) {
        #pragma unroll
        for (int u = 0; u < 4; ++u) {
            const int t = 4 * blk + 1 + u;
            const int pr = (t - 1) & 1, pw = t & 1;
            if (t < TT) {
                float pm = __shfl_up_sync(0xffffffffu, mO, 1);
                int   pe = __shfl_up_sync(0xffffffffu, e, 1);
                if (lane == 0) { pm = hM[pr][w]; pe = hE[pr][w]; }

                int   em  = max(e, pe);
                float fs  = p2n(e  - em);
                float fp  = p2n(pe - em);
                float fpg = skip ? fp : 0.f;

                float aE = fmaf(mE, fs, pm * fp)  * qb[u];         // blank 2i
                float aO = fmaf(mE + mO, fs, pm * fpg) * q1[u];    // label 2i+1
                float aX = 0.f;
                if (last) aX = (mX + mO) * fs * qb[u];             // blank 512

                float big = fmaxf(aE, aO);
                if (last) big = fmaxf(big, aX);
                int ad = (__float_as_int(big) >> 23) - 127;
                e = em + ad;
                float sc = p2n(-ad);
                mE = aE * sc;
                mO = aO * sc;
                if (last) mX = aX * sc;
                if (lane == 31) { hM[pw][w + 1] = mO; hE[pw][w + 1] = e; }
            }
            if (t + 4 < TT) {
                qb[u] = rp[0];
                q1[u] = rp[ext];
            }
            rp += VV;
            __syncthreads();
        }
    }

    // ----- readout -----
    sM[2 * tid]     = mE; sG[2 * tid]     = e;
    sM[2 * tid + 1] = mO; sG[2 * tid + 1] = e;
    if (last) { sM[2 * NTHR] = mX; sG[2 * NTHR] = e; }
    __syncthreads();
    if (tid == 0) {
        int il = 2 * sh_len, ip = il - 1;      // il in [256, 512]
        float ma = sM[il]; int ga = sG[il];
        float mb = sM[ip]; int gb = sG[ip];
        float la = (ma > 0.f) ? (float)ga + __log2f(ma) : -3.0e8f;
        float lb = (mb > 0.f) ? (float)gb + __log2f(mb) : -3.0e8f;
        float mx = fmaxf(la, lb);
        float ll2 = mx + __log2f(exp2f(la - mx) + exp2f(lb - mx));
        g_loss[b] = -ll2 * LN2F;
    }
}

// ---------------------------------------------------------------------------
// Pass 3: mean over batch + 1e-7
// ---------------------------------------------------------------------------
__global__ void finalize_kernel(float* __restrict__ out) {
    int t = threadIdx.x;
    float v = g_loss[t];
    #pragma unroll
    for (int o = 16; o > 0; o >>= 1)
        v += __shfl_xor_sync(0xffffffffu, v, o);
    if (t == 0) out[0] = v * (1.0f / (float)BB) + 1e-7f;
}

extern "C" void kernel_launch(void* const* d_in, const int* in_sizes, int n_in,
                              void* d_out, int out_size) {
    const float* y_pred = (const float*)d_in[0];
    const int*   y_true = (const int*)d_in[1];
    float*       out    = (float*)d_out;

    prob_kernel<<<(BB * TT) / 8, 256>>>(y_pred);
    ctc_kernel<<<BB, NTHR>>>(y_true);
    finalize_kernel<<<1, 32>>>(out);
}

// round 9
// speedup vs baseline: 1.8752x; 1.0061x over previous
#include <cuda_runtime.h>
#include <cuda_bf16.h>
#include <cstdint>

#define BB 32
#define TT 2048
#define VV 128
#define LL 256
#define SS 513            // 2*L+1
#define NTHR 256          // 8 warps; thread i owns states 2i, 2i+1 (+512 on i=255)
#define NWARP 8
#define EDEAD (-(1 << 28))
#define LN2F 0.6931471805599453f

// Scratch: penalty-adjusted softmax probabilities [B][T][V]  (~33.5 MB)
__device__ __align__(16) float g_p[(size_t)BB * TT * VV];
__device__ float g_loss[BB];

__device__ __forceinline__ float penalty_of(int v) {
    if (v == 0 || v == 3) return 1.0f;
    if (v == 11 || v == 15 || v == 19 || v == 25 || v == 31) return 5.0f;
    return 0.0f;
}

// 2^d, exact; flushes to 0 for d <= -127. Callers guarantee d <= 127.
__device__ __forceinline__ float p2n(int d) {
    int be = 127 + d;
    be = be < 0 ? 0 : be;
    return __int_as_float((uint32_t)be << 23);
}

// ---------------------------------------------------------------------------
// Pass 1: p[b,t,v] = softmax_v(y_pred - penalty)   (linear domain)
// ---------------------------------------------------------------------------
__global__ void prob_kernel(const float* __restrict__ y_pred) {
    int gwarp = (blockIdx.x * blockDim.x + threadIdx.x) >> 5;
    int lane  = threadIdx.x & 31;
    if (gwarp >= BB * TT) return;

    const float4* row = reinterpret_cast<const float4*>(y_pred + (size_t)gwarp * VV);
    float4 x = row[lane];
    int v0 = lane * 4;
    x.x -= penalty_of(v0 + 0);
    x.y -= penalty_of(v0 + 1);
    x.z -= penalty_of(v0 + 2);
    x.w -= penalty_of(v0 + 3);

    float m = fmaxf(fmaxf(x.x, x.y), fmaxf(x.z, x.w));
    #pragma unroll
    for (int o = 16; o > 0; o >>= 1)
        m = fmaxf(m, __shfl_xor_sync(0xffffffffu, m, o));

    float s = __expf(x.x - m) + __expf(x.y - m) + __expf(x.z - m) + __expf(x.w - m);
    #pragma unroll
    for (int o = 16; o > 0; o >>= 1)
        s += __shfl_xor_sync(0xffffffffu, s, o);

    float lse = m + __logf(s);
    float4 out;
    out.x = __expf(x.x - lse);
    out.y = __expf(x.y - lse);
    out.z = __expf(x.z - lse);
    out.w = __expf(x.w - lse);
    reinterpret_cast<float4*>(g_p + (size_t)gwarp * VV)[lane] = out;
}

// ---------------------------------------------------------------------------
// Pass 2: CTC forward. Thread i holds (mE, mO[, mX]) mantissas sharing one
// exponent frame e. Per step: one shfl pair for the neighbor's odd state,
// shared alignment factors, joint renorm. One __syncthreads per step.
// ---------------------------------------------------------------------------
__global__ void __launch_bounds__(NTHR, 1) ctc_kernel(const int* __restrict__ y_true) {
    __shared__ float hM[2][NWARP + 1];
    __shared__ int   hE[2][NWARP + 1];
    __shared__ int   sh_lab[LL];
    __shared__ int   sh_len;
    __shared__ float sM[2 * NTHR + 1];
    __shared__ int   sG[2 * NTHR + 1];

    const int b    = blockIdx.x;
    const int tid  = threadIdx.x;
    const int lane = tid & 31;
    const int w    = tid >> 5;
    const bool last = (tid == NTHR - 1);

    sh_lab[tid] = y_true[b * LL + tid];
    if (tid == 0) {
        sh_len = 0;
        hM[0][0] = 0.0f;  hM[1][0] = 0.0f;    // state -1 (never exists)
        hE[0][0] = EDEAD; hE[1][0] = EDEAD;
    }
    __syncthreads();
    if (sh_lab[tid] != 0) atomicAdd(&sh_len, 1);

    const int ext = sh_lab[tid];               // label of odd state 2*tid+1
    const bool skip = (tid > 0) && (ext != 0) && (ext != sh_lab[tid - 1]);

    const float* pb = g_p + (size_t)b * TT * VV;

    // ----- t=0 init: only states 0, 1 live (thread 0) -----
    float mE = 0.f, mO = 0.f, mX = 0.f;
    int   e  = EDEAD;
    if (tid == 0) {
        float vE = pb[0], vO = pb[ext];
        int eE = (__float_as_int(vE) >> 23) - 127;
        int eO = (__float_as_int(vO) >> 23) - 127;
        e  = max(eE, eO);
        mE = vE * p2n(-e);
        mO = vO * p2n(-e);
    }
    if (lane == 31) {
        hM[0][w + 1] = mO; hE[0][w + 1] = e;
        hM[1][w + 1] = mO; hE[1][w + 1] = e;
    }

    // prob queues for t = 1..4 (slot u consumed at t = 4*blk+1+u)
    float qb[4], q1[4];
    #pragma unroll
    for (int u = 0; u < 4; ++u) {
        const float* row = pb + (size_t)(1 + u) * VV;
        qb[u] = row[0];
        q1[u] = row[ext];
    }
    const float* rp = pb + (size_t)5 * VV;     // refill source (row t+4 at t=1)

    __syncthreads();

    for (int blk = 0; blk < 512; ++blk) {
        #pragma unroll
        for (int u = 0; u < 4; ++u) {
            const int t = 4 * blk + 1 + u;
            const int pr = (t - 1) & 1, pw = t & 1;
            if (t < TT) {
                float pm = __shfl_up_sync(0xffffffffu, mO, 1);
                int   pe = __shfl_up_sync(0xffffffffu, e, 1);
                if (lane == 0) { pm = hM[pr][w]; pe = hE[pr][w]; }

                int   em  = max(e, pe);
                float fs  = p2n(e  - em);
                float fp  = p2n(pe - em);
                float fpg = skip ? fp : 0.f;

                float aE = fmaf(mE, fs, pm * fp)  * qb[u];         // blank 2i
                float aO = fmaf(mE + mO, fs, pm * fpg) * q1[u];    // label 2i+1
                float aX = 0.f;
                if (last) aX = (mX + mO) * fs * qb[u];             // blank 512

                float big = fmaxf(aE, aO);
                if (last) big = fmaxf(big, aX);
                int ad = (__float_as_int(big) >> 23) - 127;
                e = em + ad;
                float sc = p2n(-ad);
                mE = aE * sc;
                mO = aO * sc;
                if (last) mX = aX * sc;
                if (lane == 31) { hM[pw][w + 1] = mO; hE[pw][w + 1] = e; }
            }
            if (t + 4 < TT) {
                qb[u] = rp[0];
                q1[u] = rp[ext];
            }
            rp += VV;
            __syncthreads();
        }
    }

    // ----- readout -----
    sM[2 * tid]     = mE; sG[2 * tid]     = e;
    sM[2 * tid + 1] = mO; sG[2 * tid + 1] = e;
    if (last) { sM[2 * NTHR] = mX; sG[2 * NTHR] = e; }
    __syncthreads();
    if (tid == 0) {
        int il = 2 * sh_len, ip = il - 1;      // il in [256, 512]
        float ma = sM[il]; int ga = sG[il];
        float mb = sM[ip]; int gb = sG[ip];
        float la = (ma > 0.f) ? (float)ga + __log2f(ma) : -3.0e8f;
        float lb = (mb > 0.f) ? (float)gb + __log2f(mb) : -3.0e8f;
        float mx = fmaxf(la, lb);
        float ll2 = mx + __log2f(exp2f(la - mx) + exp2f(lb - mx));
        g_loss[b] = -ll2 * LN2F;
    }
}

// ---------------------------------------------------------------------------
// Pass 3: mean over batch + 1e-7
// ---------------------------------------------------------------------------
__global__ void finalize_kernel(float* __restrict__ out) {
    int t = threadIdx.x;
    float v = g_loss[t];
    #pragma unroll
    for (int o = 16; o > 0; o >>= 1)
        v += __shfl_xor_sync(0xffffffffu, v, o);
    if (t == 0) out[0] = v * (1.0f / (float)BB) + 1e-7f;
}

extern "C" void kernel_launch(void* const* d_in, const int* in_sizes, int n_in,
                              void* d_out, int out_size) {
    const float* y_pred = (const float*)d_in[0];
    const int*   y_true = (const int*)d_in[1];
    float*       out    = (float*)d_out;

    prob_kernel<<<(BB * TT) / 8, 256>>>(y_pred);
    ctc_kernel<<<BB, NTHR>>>(y_true);
    finalize_kernel<<<1, 32>>>(out);
}